// round 7
// baseline (speedup 1.0000x reference)
#include <cuda_runtime.h>
#include <math.h>

#define BB 2
#define LL 1024
#define DD 1024
#define NN 16
#define RR 64
#define TGRP 32   // 32 t-groups of 32 steps each

// scratch (no device allocations allowed)
__device__ float g_delta[BB * LL * DD];
__device__ float g_Bt[BB * LL * NN];
__device__ float g_Ct[BB * LL * NN];
__device__ int   g_cnt[TGRP];
__device__ int   g_flag[TGRP];

__device__ __forceinline__ int ld_acquire(const int* p) {
    int v;
    asm volatile("ld.global.acquire.gpu.b32 %0, [%1];" : "=r"(v) : "l"(p));
    return v;
}

__global__ void reset_k() {
    int i = threadIdx.x;
    if (i < TGRP) { g_cnt[i] = 0; g_flag[i] = 0; }
}

// ---------------------------------------------------------------------------
// Fused kernel: blocks 0..255 produce Bt/Ct/delta (t-interleaved across both
// batch halves, bit-identical k-ascending chains); blocks 256..383 run the
// R5 scan body gated on per-32-step readiness flags.
// ---------------------------------------------------------------------------
__global__ void __launch_bounds__(256, 3) fused_k(
    const float* __restrict__ x,    // [2048, 1024]
    const float* __restrict__ W1,   // W_dt1 [1024, 64]
    const float* __restrict__ WB,   // [1024, 16]
    const float* __restrict__ WC,   // [1024, 16]
    const float* __restrict__ W2,   // W_dt2 [64, 1024]
    const float* __restrict__ A_log,
    const float* __restrict__ Dskip,
    float* __restrict__ y)
{
    __shared__ float As[8][64];
    __shared__ float W1s[64][64];
    __shared__ float WBs[64][16];
    __shared__ float WCs[64][16];
    __shared__ float Ts[8][64];

    int tid = threadIdx.x;

    if (blockIdx.x < 256) {
        // ================= PRODUCER =================
        int t0 = blockIdx.x * 4;   // rows t0..t0+3 for b=0 AND b=1
        // row map: j in 0..7 -> m = (j<4) ? t0+j : LL + t0 + (j-4)
        int r0 = tid >> 6;         // 0..3
        int nT = tid & 63;         // 0..63
        int rB = tid >> 4;         // 0..15 (valid < 8)
        int nB = tid & 15;
        bool doB = (rB < 8);

        float accT0 = 0.f, accT1 = 0.f, accB = 0.f, accC = 0.f;

        for (int k0 = 0; k0 < 1024; k0 += 64) {
            __syncthreads();
            for (int i = tid; i < 8 * 64; i += 256) {
                int rr = i >> 6, kk = i & 63;
                int m = (rr < 4) ? (t0 + rr) : (LL + t0 + rr - 4);
                As[rr][kk] = x[(size_t)m * 1024 + (k0 + kk)];
            }
            for (int i = tid; i < 64 * 64; i += 256) {
                int kk = i >> 6, nn = i & 63;
                W1s[kk][nn] = W1[(size_t)(k0 + kk) * 64 + nn];
            }
            for (int i = tid; i < 64 * 16; i += 256) {
                int kk = i >> 4, nn = i & 15;
                WBs[kk][nn] = WB[(size_t)(k0 + kk) * 16 + nn];
                WCs[kk][nn] = WC[(size_t)(k0 + kk) * 16 + nn];
            }
            __syncthreads();

#pragma unroll
            for (int k = 0; k < 64; ++k) {
                float w = W1s[k][nT];
                accT0 = fmaf(As[r0][k],     w, accT0);
                accT1 = fmaf(As[r0 + 4][k], w, accT1);
                if (doB) {
                    float a = As[rB][k];
                    accB = fmaf(a, WBs[k][nB], accB);
                    accC = fmaf(a, WCs[k][nB], accC);
                }
            }
        }

        __syncthreads();
        Ts[r0][nT]     = accT0;
        Ts[r0 + 4][nT] = accT1;
        if (doB) {
            int m = (rB < 4) ? (t0 + rB) : (LL + t0 + rB - 4);
            g_Bt[(size_t)m * 16 + nB] = accB;
            g_Ct[(size_t)m * 16 + nB] = accC;
        }
        __syncthreads();

        // delta = softplus(Ts @ W_dt2): exact delta_gemm chains
#pragma unroll
        for (int cb = 0; cb < 4; ++cb) {
            int n = cb * 256 + tid;
            float acc[8];
#pragma unroll
            for (int r = 0; r < 8; ++r) acc[r] = 0.f;
#pragma unroll
            for (int k = 0; k < 64; ++k) {
                float w = W2[(size_t)k * 1024 + n];
#pragma unroll
                for (int r = 0; r < 8; ++r)
                    acc[r] = fmaf(Ts[r][k], w, acc[r]);
            }
#pragma unroll
            for (int r = 0; r < 8; ++r) {
                float v = acc[r];
                v = fmaxf(v, 0.f) + log1pf(expf(-fabsf(v)));
                int m = (r < 4) ? (t0 + r) : (LL + t0 + r - 4);
                g_delta[(size_t)m * 1024 + n] = v;
            }
        }

        // publish: 8 producer blocks per t-group of 32 steps
        __threadfence();
        __syncthreads();
        if (tid == 0) {
            int g = t0 >> 5;                      // blockIdx.x / 8
            int prev = atomicAdd(&g_cnt[g], 1);
            if (prev == 7) {
                __threadfence();
                atomicExch(&g_flag[g], 1);
            }
        }
        return;
    }

    // ================= CONSUMER (R5 scan body, numerics untouched) =========
    int sid = blockIdx.x - 256;           // 0..127
    int b = sid >> 6;                     // 0..1
    int d = ((sid & 63) << 4) | (tid >> 4);
    int n = tid & 15;

    float An = expf(A_log[n]);
    float phi = (float)n * 0.39269908169872414f;
    float sphi, cphi;
    sincosf(phi, &sphi, &cphi);
    float hx = __fmul_rn(0.01f, cphi), hy = __fmul_rn(0.01f, sphi);
    float dsk = Dskip[d];

    size_t rowbase = ((size_t)b * LL) * DD + d;
    const float* xp = x + rowbase;
    const float* dp = g_delta + rowbase;
    const float* bp = g_Bt + ((size_t)b * LL) * NN + n;
    const float* cp = g_Ct + ((size_t)b * LL) * NN + n;
    float* yp = y + rowbase;

    // wait for t-group 0 (covers rows t=0..31 of both halves)
    if ((tid & 31) == 0) {
        while (ld_acquire(&g_flag[0]) == 0) { __nanosleep(200); }
    }
    __syncwarp();

    float xv = __ldg(xp);
    float dv = __ldg(dp);
    float bn = __ldg(bp);
    float cn = __ldg(cp);

#pragma unroll 2
    for (int t = 0; t < LL; ++t) {
        // gate the prefetch of row t+1 when it crosses into a new t-group
        if (((t + 1) & 31) == 0 && (t + 1) < LL) {
            int g = (t + 1) >> 5;
            if ((tid & 31) == 0) {
                while (ld_acquire(&g_flag[g]) == 0) { __nanosleep(200); }
            }
            __syncwarp();
        }

        int tn = (t < LL - 1) ? (t + 1) : t;
        float xv2 = __ldg(xp + (size_t)tn * DD);
        float dv2 = __ldg(dp + (size_t)tn * DD);
        float bn2 = __ldg(bp + tn * NN);
        float cn2 = __ldg(cp + tn * NN);

        // ---- fractal_compress(h, e) ----
        float mag = __fsqrt_rn(__fadd_rn(__fadd_rn(__fmul_rn(hx, hx), __fmul_rn(hy, hy)), 1e-8f));
        float ph  = atan2f(hy, __fadd_rn(hx, 1e-10f));
        float e   = __fadd_rn(1.0f, __fmul_rn(dv, An));
        float cm  = fminf(expf(__fmul_rn(e, logf(__fadd_rn(mag, 1e-8f)))), 10.0f);
        float sph, cph;
        sincosf(ph, &sph, &cph);
        float hcx = __fmul_rn(cm, cph);
        float hcy = __fmul_rn(cm, sph);

        // ---- injection on carrier phases ----
        float u   = __fmul_rn(xv, bn);
        float ijx = __fmul_rn(u, cphi);
        float ijy = __fmul_rn(u, sphi);

        // ---- resonance gate: gamma = 0.5 * cos((pa-pb)/2)^2 ----
        float pa = atan2f(ijy, __fadd_rn(ijx, 1e-10f));
        float pb = atan2f(hcy, __fadd_rn(hcx, 1e-10f));
        float cd = cosf(__fmul_rn(__fsub_rn(pa, pb), 0.5f));
        float gam = __fmul_rn(0.5f, __fmul_rn(cd, cd));

        // ---- inject + mag_squash ----
        float sx = __fadd_rn(hcx, __fmul_rn(gam, ijx));
        float sy = __fadd_rn(hcy, __fmul_rn(gam, ijy));
        float sm = __fsqrt_rn(__fadd_rn(__fadd_rn(__fmul_rn(sx, sx), __fmul_rn(sy, sy)), 1e-8f));
        float ps = atan2f(sy, __fadd_rn(sx, 1e-10f));
        float th = tanhf(sm);
        float sps, cps;
        sincosf(ps, &sps, &cps);
        hx = __fmul_rn(th, cps);
        hy = __fmul_rn(th, sps);

        // ---- readout ----
        float v = __fmul_rn(hx, cn);
        v += __shfl_xor_sync(0xffffffffu, v, 8);
        v += __shfl_xor_sync(0xffffffffu, v, 4);
        v += __shfl_xor_sync(0xffffffffu, v, 2);
        v += __shfl_xor_sync(0xffffffffu, v, 1);
        if (n == 0) yp[(size_t)t * DD] = __fadd_rn(__fmul_rn(xv, dsk), v);

        xv = xv2; dv = dv2; bn = bn2; cn = cn2;
    }
}

extern "C" void kernel_launch(void* const* d_in, const int* in_sizes, int n_in,
                              void* d_out, int out_size)
{
    const float *x = 0, *A_log = 0, *W_dt1 = 0, *W_dt2 = 0, *W_B = 0, *W_C = 0, *Dskip = 0;
    for (int i = 0; i < n_in; ++i) {
        const float* p = (const float*)d_in[i];
        int s = in_sizes[i];
        if (s == BB * LL * DD)      { if (!x) x = p; }
        else if (s == NN)           { if (!A_log) A_log = p; }
        else if (s == DD * RR)      { if (!W_dt1) W_dt1 = p; else W_dt2 = p; }
        else if (s == DD * NN)      { if (!W_B) W_B = p; else W_C = p; }
        else if (s == DD)           { if (!Dskip) Dskip = p; }
    }
    float* y = (float*)d_out;

    reset_k<<<1, 32>>>();
    // 256 producer blocks + 128 scan blocks, all co-resident (3 blocks/SM cap)
    fused_k<<<384, 256>>>(x, W_dt1, W_B, W_C, W_dt2, A_log, Dskip, y);
}

// round 8
// speedup vs baseline: 1.2875x; 1.2875x over previous
#include <cuda_runtime.h>
#include <math.h>

#define BB 2
#define LL 1024
#define DD 1024
#define NN 16
#define RR 64

// scratch (no device allocations allowed)
__device__ float g_delta[BB * LL * DD];
__device__ float g_Bt[BB * LL * NN];
__device__ float g_Ct[BB * LL * NN];

// ---------------------------------------------------------------------------
// Producer: tmp (smem-resident), Bt, Ct, delta in ONE kernel.
// TM=4 rows/block -> grid 512 (3.5 blocks/SM). Every output keeps the exact
// k-ascending fmaf chain + identical softplus => bit-identical delta/Bt/Ct.
// ---------------------------------------------------------------------------
__global__ void __launch_bounds__(256) producer_k(
    const float* __restrict__ A,   // x: [2048, 1024]
    const float* __restrict__ W1,  // W_dt1 [1024, 64]
    const float* __restrict__ WB,  // [1024, 16]
    const float* __restrict__ WC,  // [1024, 16]
    const float* __restrict__ W2)  // W_dt2 [64, 1024]
{
    __shared__ float As[4][64];
    __shared__ float W1s[64][64];
    __shared__ float WBs[64][16];
    __shared__ float WCs[64][16];
    __shared__ float Ts[4][64];

    int tid = threadIdx.x;
    int m0 = blockIdx.x * 4;      // rows m0..m0+3 of the flattened [2048, *]

    int r0 = tid >> 6;            // 0..3  (tmp row)
    int nT = tid & 63;            // 0..63 (tmp col)
    int rB = tid >> 4;            // btct row (valid < 4)
    int nB = tid & 15;
    bool doB = (tid < 64);

    float accT = 0.f, accB = 0.f, accC = 0.f;

    for (int k0 = 0; k0 < 1024; k0 += 64) {
        __syncthreads();
        // stage x tile 4x64 (one element per thread)
        As[r0][nT] = A[(size_t)(m0 + r0) * 1024 + (k0 + nT)];
        // stage W_dt1 chunk 64x64
        for (int i = tid; i < 64 * 64; i += 256) {
            int kk = i >> 6, nn = i & 63;
            W1s[kk][nn] = W1[(size_t)(k0 + kk) * 64 + nn];
        }
        // stage WB/WC chunks 64x16
        for (int i = tid; i < 64 * 16; i += 256) {
            int kk = i >> 4, nn = i & 15;
            WBs[kk][nn] = WB[(size_t)(k0 + kk) * 16 + nn];
            WCs[kk][nn] = WC[(size_t)(k0 + kk) * 16 + nn];
        }
        __syncthreads();

#pragma unroll
        for (int k = 0; k < 64; ++k) {
            accT = fmaf(As[r0][k], W1s[k][nT], accT);
            if (doB) {
                float a = As[rB][k];
                accB = fmaf(a, WBs[k][nB], accB);
                accC = fmaf(a, WCs[k][nB], accC);
            }
        }
    }

    __syncthreads();
    Ts[r0][nT] = accT;
    if (doB) {
        g_Bt[(size_t)(m0 + rB) * 16 + nB] = accB;
        g_Ct[(size_t)(m0 + rB) * 16 + nB] = accC;
    }
    __syncthreads();

    // delta = softplus(Ts @ W_dt2): exact 64-term k-ascending chains,
    // identical softplus formula.
#pragma unroll
    for (int cb = 0; cb < 4; ++cb) {
        int n = cb * 256 + tid;
        float acc[4] = {0.f, 0.f, 0.f, 0.f};
#pragma unroll
        for (int k = 0; k < 64; ++k) {
            float w = W2[(size_t)k * 1024 + n];
#pragma unroll
            for (int r = 0; r < 4; ++r)
                acc[r] = fmaf(Ts[r][k], w, acc[r]);
        }
#pragma unroll
        for (int r = 0; r < 4; ++r) {
            float v = acc[r];
            v = fmaxf(v, 0.f) + log1pf(expf(-fabsf(v)));
            g_delta[(size_t)(m0 + r) * 1024 + n] = v;
        }
    }
}

// ---------------- sequential resonance scan (R5 verbatim — best config) -----
__global__ void __launch_bounds__(256, 1) scan_k(
    const float* __restrict__ x, const float* __restrict__ A_log,
    const float* __restrict__ Dskip, float* __restrict__ y)
{
    int tid = threadIdx.x;
    int bid = blockIdx.x;                 // 0..127
    int b = bid >> 6;                     // 0..1
    int d = ((bid & 63) << 4) | (tid >> 4);
    int n = tid & 15;

    float An = expf(A_log[n]);
    float phi = (float)n * 0.39269908169872414f;
    float sphi, cphi;
    sincosf(phi, &sphi, &cphi);
    float hx = __fmul_rn(0.01f, cphi), hy = __fmul_rn(0.01f, sphi);
    float dsk = Dskip[d];

    size_t rowbase = ((size_t)b * LL) * DD + d;
    const float* xp = x + rowbase;
    const float* dp = g_delta + rowbase;
    const float* bp = g_Bt + ((size_t)b * LL) * NN + n;
    const float* cp = g_Ct + ((size_t)b * LL) * NN + n;
    float* yp = y + rowbase;

    float xv = __ldg(xp);
    float dv = __ldg(dp);
    float bn = __ldg(bp);
    float cn = __ldg(cp);

#pragma unroll 2
    for (int t = 0; t < LL; ++t) {
        int tn = (t < LL - 1) ? (t + 1) : t;
        float xv2 = __ldg(xp + (size_t)tn * DD);
        float dv2 = __ldg(dp + (size_t)tn * DD);
        float bn2 = __ldg(bp + tn * NN);
        float cn2 = __ldg(cp + tn * NN);

        // ---- fractal_compress(h, e) ----
        float mag = __fsqrt_rn(__fadd_rn(__fadd_rn(__fmul_rn(hx, hx), __fmul_rn(hy, hy)), 1e-8f));
        float ph  = atan2f(hy, __fadd_rn(hx, 1e-10f));
        float e   = __fadd_rn(1.0f, __fmul_rn(dv, An));
        float cm  = fminf(expf(__fmul_rn(e, logf(__fadd_rn(mag, 1e-8f)))), 10.0f);
        float sph, cph;
        sincosf(ph, &sph, &cph);
        float hcx = __fmul_rn(cm, cph);
        float hcy = __fmul_rn(cm, sph);

        // ---- injection on carrier phases ----
        float u   = __fmul_rn(xv, bn);
        float ijx = __fmul_rn(u, cphi);
        float ijy = __fmul_rn(u, sphi);

        // ---- resonance gate: gamma = 0.5 * cos((pa-pb)/2)^2 ----
        float pa = atan2f(ijy, __fadd_rn(ijx, 1e-10f));
        float pb = atan2f(hcy, __fadd_rn(hcx, 1e-10f));
        float cd = cosf(__fmul_rn(__fsub_rn(pa, pb), 0.5f));
        float gam = __fmul_rn(0.5f, __fmul_rn(cd, cd));

        // ---- inject + mag_squash ----
        float sx = __fadd_rn(hcx, __fmul_rn(gam, ijx));
        float sy = __fadd_rn(hcy, __fmul_rn(gam, ijy));
        float sm = __fsqrt_rn(__fadd_rn(__fadd_rn(__fmul_rn(sx, sx), __fmul_rn(sy, sy)), 1e-8f));
        float ps = atan2f(sy, __fadd_rn(sx, 1e-10f));
        float th = tanhf(sm);
        float sps, cps;
        sincosf(ps, &sps, &cps);
        hx = __fmul_rn(th, cps);
        hy = __fmul_rn(th, sps);

        // ---- readout ----
        float v = __fmul_rn(hx, cn);
        v += __shfl_xor_sync(0xffffffffu, v, 8);
        v += __shfl_xor_sync(0xffffffffu, v, 4);
        v += __shfl_xor_sync(0xffffffffu, v, 2);
        v += __shfl_xor_sync(0xffffffffu, v, 1);
        if (n == 0) yp[(size_t)t * DD] = __fadd_rn(__fmul_rn(xv, dsk), v);

        xv = xv2; dv = dv2; bn = bn2; cn = cn2;
    }
}

extern "C" void kernel_launch(void* const* d_in, const int* in_sizes, int n_in,
                              void* d_out, int out_size)
{
    const float *x = 0, *A_log = 0, *W_dt1 = 0, *W_dt2 = 0, *W_B = 0, *W_C = 0, *Dskip = 0;
    for (int i = 0; i < n_in; ++i) {
        const float* p = (const float*)d_in[i];
        int s = in_sizes[i];
        if (s == BB * LL * DD)      { if (!x) x = p; }
        else if (s == NN)           { if (!A_log) A_log = p; }
        else if (s == DD * RR)      { if (!W_dt1) W_dt1 = p; else W_dt2 = p; }
        else if (s == DD * NN)      { if (!W_B) W_B = p; else W_C = p; }
        else if (s == DD)           { if (!Dskip) Dskip = p; }
    }
    float* y = (float*)d_out;

    // single producer launch: Bt, Ct, delta (bit-identical chains)
    producer_k<<<512, 256>>>(x, W_dt1, W_B, W_C, W_dt2);
    // sequential scan (R5 verbatim)
    scan_k<<<128, 256>>>(x, A_log, Dskip, y);
}

// round 9
// speedup vs baseline: 1.3984x; 1.0861x over previous
#include <cuda_runtime.h>
#include <math.h>

#define BB 2
#define LL 1024
#define DD 1024
#define NN 16
#define RR 64

// scratch (no device allocations allowed)
__device__ float g_delta[BB * LL * DD];
__device__ float g_Bt[BB * LL * NN];
__device__ float g_Ct[BB * LL * NN];

// ---------------------------------------------------------------------------
// Producer: one warp per output row m. Stage x row in smem once, then:
//   lanes 0..15 : tmp cols 4L..4L+3   (float4 W1 loads, 4 fmaf chains)
//   lanes 16..23: Bt  cols 2j..2j+1   (float2 WB loads)
//   lanes 24..31: Ct  cols 2j..2j+1   (float2 WC loads)
// then the same warp computes delta row = softplus(tmp @ W_dt2) from the
// smem-resident tmp. Every chain is the exact k-ascending fmaf sequence with
// the identical softplus => bit-identical delta/Bt/Ct to the passing kernel.
// ---------------------------------------------------------------------------
__global__ void __launch_bounds__(64) producer_k(
    const float* __restrict__ x,   // [2048, 1024]
    const float* __restrict__ W1,  // [1024, 64]
    const float* __restrict__ WB,  // [1024, 16]
    const float* __restrict__ WC,  // [1024, 16]
    const float* __restrict__ W2)  // [64, 1024]
{
    __shared__ float xs[2][1024];
    __shared__ float ts[2][64];

    int lane = threadIdx.x & 31;
    int w = threadIdx.x >> 5;            // 0..1
    int m = blockIdx.x * 2 + w;          // row 0..2047

    // stage this warp's x row (8 float4 per lane, coalesced)
    const float4* xrow = (const float4*)(x + (size_t)m * 1024);
    float4* xsv = (float4*)xs[w];
#pragma unroll
    for (int i = 0; i < 8; ++i)
        xsv[lane + 32 * i] = xrow[lane + 32 * i];
    __syncwarp();

    if (lane < 16) {
        // tmp cols 4*lane .. 4*lane+3
        float ax = 0.f, ay = 0.f, az = 0.f, aw = 0.f;
        const float4* w1p = (const float4*)W1 + lane;   // W1[k][4*lane], stride 16 float4
        for (int k = 0; k < 1024; ++k) {
            float a = xs[w][k];
            float4 wv = w1p[(size_t)k * 16];
            ax = fmaf(a, wv.x, ax);
            ay = fmaf(a, wv.y, ay);
            az = fmaf(a, wv.z, az);
            aw = fmaf(a, wv.w, aw);
        }
        float4 r; r.x = ax; r.y = ay; r.z = az; r.w = aw;
        ((float4*)ts[w])[lane] = r;
    } else if (lane < 24) {
        // Bt cols 2j..2j+1
        int j = lane - 16;
        float bx = 0.f, by = 0.f;
        const float2* wbp = (const float2*)WB + j;      // WB[k][2j], stride 8 float2
        for (int k = 0; k < 1024; ++k) {
            float a = xs[w][k];
            float2 wv = wbp[(size_t)k * 8];
            bx = fmaf(a, wv.x, bx);
            by = fmaf(a, wv.y, by);
        }
        float2 r; r.x = bx; r.y = by;
        ((float2*)(g_Bt + (size_t)m * 16))[j] = r;
    } else {
        // Ct cols 2j..2j+1
        int j = lane - 24;
        float cx = 0.f, cy = 0.f;
        const float2* wcp = (const float2*)WC + j;
        for (int k = 0; k < 1024; ++k) {
            float a = xs[w][k];
            float2 wv = wcp[(size_t)k * 8];
            cx = fmaf(a, wv.x, cx);
            cy = fmaf(a, wv.y, cy);
        }
        float2 r; r.x = cx; r.y = cy;
        ((float2*)(g_Ct + (size_t)m * 16))[j] = r;
    }
    __syncwarp();

    // delta row: softplus(ts[w] @ W_dt2), 4 cols per lane per chunk
#pragma unroll 1
    for (int cb = 0; cb < 8; ++cb) {
        int n = cb * 128 + lane * 4;
        float ax = 0.f, ay = 0.f, az = 0.f, aw = 0.f;
        const float4* w2p = (const float4*)(W2 + n);    // W2[k][n..n+3], stride 256 float4
#pragma unroll
        for (int k = 0; k < 64; ++k) {
            float a = ts[w][k];
            float4 wv = w2p[(size_t)k * 256];
            ax = fmaf(a, wv.x, ax);
            ay = fmaf(a, wv.y, ay);
            az = fmaf(a, wv.z, az);
            aw = fmaf(a, wv.w, aw);
        }
        float4 r;
        r.x = fmaxf(ax, 0.f) + log1pf(expf(-fabsf(ax)));
        r.y = fmaxf(ay, 0.f) + log1pf(expf(-fabsf(ay)));
        r.z = fmaxf(az, 0.f) + log1pf(expf(-fabsf(az)));
        r.w = fmaxf(aw, 0.f) + log1pf(expf(-fabsf(aw)));
        *((float4*)(g_delta + (size_t)m * 1024 + n)) = r;
    }
}

// ---------------- sequential resonance scan (R5 verbatim — best config) -----
__global__ void __launch_bounds__(256, 1) scan_k(
    const float* __restrict__ x, const float* __restrict__ A_log,
    const float* __restrict__ Dskip, float* __restrict__ y)
{
    int tid = threadIdx.x;
    int bid = blockIdx.x;                 // 0..127
    int b = bid >> 6;                     // 0..1
    int d = ((bid & 63) << 4) | (tid >> 4);
    int n = tid & 15;

    float An = expf(A_log[n]);
    float phi = (float)n * 0.39269908169872414f;
    float sphi, cphi;
    sincosf(phi, &sphi, &cphi);
    float hx = __fmul_rn(0.01f, cphi), hy = __fmul_rn(0.01f, sphi);
    float dsk = Dskip[d];

    size_t rowbase = ((size_t)b * LL) * DD + d;
    const float* xp = x + rowbase;
    const float* dp = g_delta + rowbase;
    const float* bp = g_Bt + ((size_t)b * LL) * NN + n;
    const float* cp = g_Ct + ((size_t)b * LL) * NN + n;
    float* yp = y + rowbase;

    float xv = __ldg(xp);
    float dv = __ldg(dp);
    float bn = __ldg(bp);
    float cn = __ldg(cp);

#pragma unroll 2
    for (int t = 0; t < LL; ++t) {
        int tn = (t < LL - 1) ? (t + 1) : t;
        float xv2 = __ldg(xp + (size_t)tn * DD);
        float dv2 = __ldg(dp + (size_t)tn * DD);
        float bn2 = __ldg(bp + tn * NN);
        float cn2 = __ldg(cp + tn * NN);

        // ---- fractal_compress(h, e) ----
        float mag = __fsqrt_rn(__fadd_rn(__fadd_rn(__fmul_rn(hx, hx), __fmul_rn(hy, hy)), 1e-8f));
        float ph  = atan2f(hy, __fadd_rn(hx, 1e-10f));
        float e   = __fadd_rn(1.0f, __fmul_rn(dv, An));
        float cm  = fminf(expf(__fmul_rn(e, logf(__fadd_rn(mag, 1e-8f)))), 10.0f);
        float sph, cph;
        sincosf(ph, &sph, &cph);
        float hcx = __fmul_rn(cm, cph);
        float hcy = __fmul_rn(cm, sph);

        // ---- injection on carrier phases ----
        float u   = __fmul_rn(xv, bn);
        float ijx = __fmul_rn(u, cphi);
        float ijy = __fmul_rn(u, sphi);

        // ---- resonance gate: gamma = 0.5 * cos((pa-pb)/2)^2 ----
        float pa = atan2f(ijy, __fadd_rn(ijx, 1e-10f));
        float pb = atan2f(hcy, __fadd_rn(hcx, 1e-10f));
        float cd = cosf(__fmul_rn(__fsub_rn(pa, pb), 0.5f));
        float gam = __fmul_rn(0.5f, __fmul_rn(cd, cd));

        // ---- inject + mag_squash ----
        float sx = __fadd_rn(hcx, __fmul_rn(gam, ijx));
        float sy = __fadd_rn(hcy, __fmul_rn(gam, ijy));
        float sm = __fsqrt_rn(__fadd_rn(__fadd_rn(__fmul_rn(sx, sx), __fmul_rn(sy, sy)), 1e-8f));
        float ps = atan2f(sy, __fadd_rn(sx, 1e-10f));
        float th = tanhf(sm);
        float sps, cps;
        sincosf(ps, &sps, &cps);
        hx = __fmul_rn(th, cps);
        hy = __fmul_rn(th, sps);

        // ---- readout ----
        float v = __fmul_rn(hx, cn);
        v += __shfl_xor_sync(0xffffffffu, v, 8);
        v += __shfl_xor_sync(0xffffffffu, v, 4);
        v += __shfl_xor_sync(0xffffffffu, v, 2);
        v += __shfl_xor_sync(0xffffffffu, v, 1);
        if (n == 0) yp[(size_t)t * DD] = __fadd_rn(__fmul_rn(xv, dsk), v);

        xv = xv2; dv = dv2; bn = bn2; cn = cn2;
    }
}

extern "C" void kernel_launch(void* const* d_in, const int* in_sizes, int n_in,
                              void* d_out, int out_size)
{
    const float *x = 0, *A_log = 0, *W_dt1 = 0, *W_dt2 = 0, *W_B = 0, *W_C = 0, *Dskip = 0;
    for (int i = 0; i < n_in; ++i) {
        const float* p = (const float*)d_in[i];
        int s = in_sizes[i];
        if (s == BB * LL * DD)      { if (!x) x = p; }
        else if (s == NN)           { if (!A_log) A_log = p; }
        else if (s == DD * RR)      { if (!W_dt1) W_dt1 = p; else W_dt2 = p; }
        else if (s == DD * NN)      { if (!W_B) W_B = p; else W_C = p; }
        else if (s == DD)           { if (!Dskip) Dskip = p; }
    }
    float* y = (float*)d_out;

    // one producer launch: Bt, Ct, delta (bit-identical chains, warp-per-row)
    producer_k<<<1024, 64>>>(x, W_dt1, W_B, W_C, W_dt2);
    // sequential scan (R5 verbatim — per-warp latency floor)
    scan_k<<<128, 256>>>(x, A_log, Dskip, y);
}